// round 14
// baseline (speedup 1.0000x reference)
#include <cuda_runtime.h>
#include <cuda_pipeline.h>
#include <math.h>

// Fixed problem shapes
#define B_    4
#define N_    10
#define K_    5
#define Q_    512
#define D_    1536
#define D4_   384            // float4 per row
#define R50_  (N_ * K_)      // 50 support rows per batch

#define SLC_  12             // float4 columns per slice
#define NSL_  32             // slices per batch
#define NBLK_ 128            // B * NSL, one co-resident wave
#define NT_   768
#define NW_   24
#define NP2_  (B_ * N_)      // 40 phase-2 blocks
#define PITCH_ 13            // padded pitch

// Scratch (allocation-free device globals)
__device__ float2   g_dn[B_ * R50_ * NSL_];  // per-(b,n,k,slice) {dot, nrm} partials
__device__ float    g_ss[NBLK_];             // per-(b,slice) sum of squares
__device__ unsigned g_cnt;                   // monotone wrap-safe barrier counter

__global__ void __launch_bounds__(NT_, 1)
fused_kernel(const float4* __restrict__ q4,
             const float4* __restrict__ sup4,
             float* __restrict__ out) {
    const int tid  = threadIdx.x;
    const int lane = tid & 31;
    const int wid  = tid >> 5;
    const int bid  = blockIdx.x;

    // s_part (phase-1 column partials) and s_dn (dot/nrm partials) are
    // time-disjoint -> share one buffer to stay under the 48KB static limit.
    __shared__ __align__(16) char s_u[64 * PITCH_ * 16];      // 13.3 KB
    float4* s_part = (float4*)s_u;                            // [64][PITCH]
    float2* s_dn   = (float2*)s_u;                            // [50][PITCH]
    __shared__ float4 s_sv[K_ * D4_];                         // support tile (30 KB)
    __shared__ float4 s_qb[SLC_];                             // this block's qbar slice
    __shared__ float  s_wred[NW_];
    __shared__ float  s_dk[K_ + 3], s_nk[K_ + 3];
    __shared__ float  s_w[K_];
    __shared__ float  s_c;

    const bool is_p2 = (bid < NP2_);
    const int  b  = bid >> 5;          // batch
    const int  sl = bid & 31;          // column slice

    // ---- phase-2 support tile -> shared via cp.async (no registers held) ----
    if (is_p2) {
        const float4* sp = sup4 + (size_t)bid * K_ * D4_;
        for (int i = tid; i < K_ * D4_; i += NT_)
            __pipeline_memcpy_async(&s_sv[i], &sp[i], 16);
        __pipeline_commit();
    }

    // ---- support slice for distributed dots: 50 rows x 12 cols ----
    const int r = tid / SLC_;              // 0..63 (row-group / support row)
    const int c = tid - r * SLC_;          // 0..11
    float4 svp;
    if (r < R50_)
        svp = sup4[((size_t)(b * R50_ + r)) * D4_ + sl * SLC_ + c];

    // ============ Phase 1: column-sliced query stats ============
    {
        const float4* qp = q4 + ((size_t)(b * Q_ + r)) * D4_ + sl * SLC_ + c;
        float4 s = make_float4(0.f, 0.f, 0.f, 0.f);
        float ss = 0.f;
        #pragma unroll
        for (int i = 0; i < 8; i++) {          // rows r + 64*i
            float4 v = qp[(size_t)(64 * i) * D4_];
            s.x += v.x; s.y += v.y; s.z += v.z; s.w += v.w;
            ss += v.x * v.x + v.y * v.y + v.z * v.z + v.w * v.w;
        }
        s_part[r * PITCH_ + c] = s;

        #pragma unroll
        for (int off = 16; off > 0; off >>= 1)
            ss += __shfl_down_sync(0xffffffffu, ss, off);
        if (lane == 0) s_wred[wid] = ss;
        __syncthreads();

        if (tid == 0) {
            float t = 0.f;
            #pragma unroll
            for (int w = 0; w < NW_; w++) t += s_wred[w];
            g_ss[bid] = t;
        }
        // fold 64 row-group partials -> qbar slice (one warp per column)
        if (wid < SLC_) {
            float4 a  = s_part[lane * PITCH_ + wid];
            float4 b2 = s_part[(lane + 32) * PITCH_ + wid];
            a.x += b2.x; a.y += b2.y; a.z += b2.z; a.w += b2.w;
            #pragma unroll
            for (int off = 16; off > 0; off >>= 1) {
                a.x += __shfl_down_sync(0xffffffffu, a.x, off);
                a.y += __shfl_down_sync(0xffffffffu, a.y, off);
                a.z += __shfl_down_sync(0xffffffffu, a.z, off);
                a.w += __shfl_down_sync(0xffffffffu, a.w, off);
            }
            if (lane == 0) {
                const float invQ = 1.0f / Q_;
                a.x *= invQ; a.y *= invQ; a.z *= invQ; a.w *= invQ;
                s_qb[wid] = a;                 // qbar slice stays local!
            }
        }
    }
    __syncthreads();

    // ============ Phase 1.5: distributed dot/nrm partials ============
    if (r < R50_) {
        float4 qb = s_qb[c];
        float dotp = svp.x * qb.x + svp.y * qb.y + svp.z * qb.z + svp.w * qb.w;
        float nrmp = svp.x * svp.x + svp.y * svp.y + svp.z * svp.z + svp.w * svp.w;
        s_dn[r * PITCH_ + c] = make_float2(dotp, nrmp);
    }
    __syncthreads();
    if (tid < R50_) {
        float dk = 0.f, nk = 0.f;
        #pragma unroll
        for (int cc = 0; cc < SLC_; cc++) {
            float2 v = s_dn[tid * PITCH_ + cc];
            dk += v.x; nk += v.y;
        }
        g_dn[((size_t)(b * R50_ + tid)) * NSL_ + sl] = make_float2(dk, nk);
    }

    // ============ Barrier: all arrive, only phase-2 blocks spin ============
    __threadfence();
    __syncthreads();
    if (tid == 0) {
        unsigned old = atomicAdd(&g_cnt, 1u);
        if (is_p2) {
            unsigned target = old - (old & (NBLK_ - 1)) + NBLK_;   // wrap-safe
            while ((int)(*(volatile unsigned*)&g_cnt - target) < 0) { }
            __threadfence();
        }
    }
    if (!is_p2) return;
    __syncthreads();

    // ============ Phase 2: tiny tail (40 blocks) ============
    const int bn = bid;
    const int bb = bn / N_;

    __pipeline_wait_prior(0);                 // s_sv landed long ago

    if (wid < K_) {
        // reduce this k's 32 slice-partials: one coalesced 256B float2 read
        float2 v = g_dn[((size_t)(bn * K_ + wid)) * NSL_ + lane];
        float dk = v.x, nk = v.y;
        #pragma unroll
        for (int off = 16; off > 0; off >>= 1) {
            dk += __shfl_down_sync(0xffffffffu, dk, off);
            nk += __shfl_down_sync(0xffffffffu, nk, off);
        }
        if (lane == 0) { s_dk[wid] = dk; s_nk[wid] = nk; }
    } else if (wid == K_) {
        float cv = g_ss[bb * NSL_ + lane];
        #pragma unroll
        for (int off = 16; off > 0; off >>= 1)
            cv += __shfl_down_sync(0xffffffffu, cv, off);
        if (lane == 0) s_c = cv * (1.0f / Q_);
    }
    __syncthreads();

    // softmax across 5 lanes of warp 0 (lanes 5..7 padded)
    if (wid == 0 && lane < 8) {
        const bool valid = (lane < K_);
        float t = valid ? tanhf(-(s_nk[lane] - 2.0f * s_dk[lane] + s_c)) : -1e30f;
        float m = t;
        #pragma unroll
        for (int off = 4; off > 0; off >>= 1)
            m = fmaxf(m, __shfl_xor_sync(0xffu, m, off, 8));
        float e = valid ? __expf(t - m) : 0.f;
        float Z = e;
        #pragma unroll
        for (int off = 4; off > 0; off >>= 1)
            Z += __shfl_xor_sync(0xffu, Z, off, 8);
        if (valid) {
            float wk = e / Z;
            s_w[lane] = wk;
            out[(size_t)B_ * N_ * D_ + bn * K_ + lane] = wk;   // qgw
        }
    }
    __syncthreads();

    if (tid < D4_) {
        float4 acc = make_float4(0.f, 0.f, 0.f, 0.f);
        #pragma unroll
        for (int k = 0; k < K_; k++) {
            float wk = s_w[k];
            float4 sv = s_sv[k * D4_ + tid];
            acc.x += wk * sv.x; acc.y += wk * sv.y;
            acc.z += wk * sv.z; acc.w += wk * sv.w;
        }
        ((float4*)out)[(size_t)bn * D4_ + tid] = acc;          // agg
    }
}

extern "C" void kernel_launch(void* const* d_in, const int* in_sizes, int n_in,
                              void* d_out, int out_size) {
    const float4* support = (const float4*)d_in[0];
    const float4* query   = (const float4*)d_in[1];
    float* out = (float*)d_out;

    fused_kernel<<<NBLK_, NT_>>>(query, support, out);
}

// round 16
// speedup vs baseline: 1.0030x; 1.0030x over previous
#include <cuda_runtime.h>
#include <cuda_pipeline.h>
#include <math.h>

// Fixed problem shapes
#define B_    4
#define N_    10
#define K_    5
#define Q_    512
#define D_    1536
#define D4_   384            // float4 per row

#define NSL_  12             // column slices per batch (32 float4 each)
#define SLW_  32             // float4 columns per slice
#define NRG_  3              // row groups per batch
#define NBLK_ (B_ * NSL_ * NRG_)   // 144 blocks (<=148 SMs: one wave)
#define NT_   768            // 24 thread-row-groups x 32 columns
#define NW_   24
#define NP2_  (B_ * N_)      // 40 phase-2 blocks

// row-group boundaries: 171, 171, 170
__device__ __constant__ int c_rg_lo[NRG_ + 1] = {0, 171, 342, 512};

// Scratch (allocation-free device globals)
__device__ float4   g_qsum[B_ * NRG_ * D4_];  // per-(b,rg) column sums
__device__ float    g_ss[NBLK_];              // per-block sum of squares
__device__ unsigned g_cnt;                    // monotone barrier counter

__global__ void __launch_bounds__(NT_, 1)
fused_kernel(const float4* __restrict__ q4,
             const float4* __restrict__ sup4,
             float* __restrict__ out) {
    const int tid  = threadIdx.x;
    const int lane = tid & 31;
    const int wid  = tid >> 5;
    const int bid  = blockIdx.x;

    __shared__ float4 s_part[24 * SLW_];      // per-(thread-rg, col) partials (12 KB)
    __shared__ float4 s_sv[K_ * D4_];         // phase-2 support tile (30 KB)
    __shared__ float  s_wred[NW_];
    __shared__ float  s_red[2 * K_ * 12];
    __shared__ float  s_dk_unused;            // (kept layout simple)
    __shared__ float  s_w[K_];
    __shared__ float  s_c;

    const bool is_p2 = (bid < NP2_);

    // ---- phase-2 support tile -> shared via cp.async (issued first) ----
    if (is_p2) {
        const float4* sp = sup4 + (size_t)bid * K_ * D4_;
        for (int i = tid; i < K_ * D4_; i += NT_)
            __pipeline_memcpy_async(&s_sv[i], &sp[i], 16);
        __pipeline_commit();
    }

    // ============ Phase 1: (batch, col-slice, row-group) query stats ============
    {
        const int b   = bid / (NSL_ * NRG_);
        const int rem = bid - b * (NSL_ * NRG_);
        const int sl  = rem / NRG_;
        const int rg  = rem - sl * NRG_;

        const int trg = tid >> 5;             // thread row-group 0..23 (== wid)
        const int c   = tid & 31;             // column-in-slice 0..31

        const int r_lo = c_rg_lo[rg], r_hi = c_rg_lo[rg + 1];
        const float4* qp = q4 + ((size_t)(b * Q_ + r_lo + trg)) * D4_ + sl * SLW_ + c;

        float4 s = make_float4(0.f, 0.f, 0.f, 0.f);
        float ss = 0.f;
        #pragma unroll
        for (int i = 0; i < 8; i++) {         // rows r_lo + trg + 24*i
            if (r_lo + trg + 24 * i < r_hi) {
                float4 v = qp[(size_t)(24 * i) * D4_];
                s.x += v.x; s.y += v.y; s.z += v.z; s.w += v.w;
                ss += v.x * v.x + v.y * v.y + v.z * v.z + v.w * v.w;
            }
        }
        s_part[trg * SLW_ + c] = s;

        #pragma unroll
        for (int off = 16; off > 0; off >>= 1)
            ss += __shfl_down_sync(0xffffffffu, ss, off);
        if (lane == 0) s_wred[wid] = ss;
        __syncthreads();

        if (tid == 0) {
            float t = 0.f;
            #pragma unroll
            for (int w = 0; w < NW_; w++) t += s_wred[w];
            g_ss[bid] = t;
        }
        // fold 24 thread-rg partials -> per-column sums; write coalesced 512B
        if (tid < 128) {                       // tid = c4*4 + comp
            const float* pf = (const float*)s_part;
            float a = 0.f;
            #pragma unroll
            for (int j = 0; j < 24; j++)
                a += pf[j * (SLW_ * 4) + tid];
            float* gq = (float*)&g_qsum[((size_t)(b * NRG_ + rg)) * D4_ + sl * SLW_];
            gq[tid] = a;
        }
    }

    // ============ Barrier: all arrive, only phase-2 blocks spin ============
    __threadfence();
    __syncthreads();
    if (tid == 0) {
        unsigned old = atomicAdd(&g_cnt, 1u);
        if (is_p2) {
            unsigned target = old - (old % NBLK_) + NBLK_;   // wrap-safe
            while ((int)(*(volatile unsigned*)&g_cnt - target) < 0) { }
            __threadfence();
        }
    }
    if (!is_p2) return;
    __syncthreads();

    // ============ Phase 2: weights + aggregation (40 blocks) ============
    const int bn = bid;
    const int bb = bn / N_;

    __pipeline_wait_prior(0);                 // s_sv landed long ago

    // c_b = mean_q ||q||^2 over this batch's 36 block partials (warp 12)
    if (wid == 12) {
        float cv = g_ss[bb * (NSL_ * NRG_) + lane]
                 + ((lane < 4) ? g_ss[bb * (NSL_ * NRG_) + 32 + lane] : 0.f);
        #pragma unroll
        for (int off = 16; off > 0; off >>= 1)
            cv += __shfl_down_sync(0xffffffffu, cv, off);
        if (lane == 0) s_c = cv * (1.0f / Q_);
    }

    if (tid < D4_) {
        // qbar column: 3 overlapped L2 loads (row-group partials)
        const float4* gq = g_qsum + (size_t)bb * NRG_ * D4_ + tid;
        float4 a0 = gq[0], a1 = gq[D4_], a2 = gq[2 * D4_];
        float4 qb;
        const float invQ = 1.0f / Q_;
        qb.x = (a0.x + a1.x + a2.x) * invQ;
        qb.y = (a0.y + a1.y + a2.y) * invQ;
        qb.z = (a0.z + a1.z + a2.z) * invQ;
        qb.w = (a0.w + a1.w + a2.w) * invQ;

        float dot[K_], nrm[K_];
        #pragma unroll
        for (int k = 0; k < K_; k++) {
            float4 sv = s_sv[k * D4_ + tid];
            dot[k] = sv.x * qb.x + sv.y * qb.y + sv.z * qb.z + sv.w * qb.w;
            nrm[k] = sv.x * sv.x + sv.y * sv.y + sv.z * sv.z + sv.w * sv.w;
        }
        #pragma unroll
        for (int k = 0; k < K_; k++) {
            float dk = dot[k], nk = nrm[k];
            #pragma unroll
            for (int off = 16; off > 0; off >>= 1) {
                dk += __shfl_down_sync(0xffffffffu, dk, off);
                nk += __shfl_down_sync(0xffffffffu, nk, off);
            }
            if (lane == 0) {
                s_red[k * 12 + wid]        = dk;
                s_red[(K_ + k) * 12 + wid] = nk;
            }
        }
    }
    __syncthreads();

    // softmax across 5 lanes of warp 0 (lanes 5..7 padded)
    if (wid == 0 && lane < 8) {
        const bool valid = (lane < K_);
        float t = -1e30f;
        if (valid) {
            float dk = 0.f, nk = 0.f;
            #pragma unroll
            for (int w = 0; w < 12; w++) {
                dk += s_red[lane * 12 + w];
                nk += s_red[(K_ + lane) * 12 + w];
            }
            t = tanhf(-(nk - 2.0f * dk + s_c));
        }
        float m = t;
        #pragma unroll
        for (int off = 4; off > 0; off >>= 1)
            m = fmaxf(m, __shfl_xor_sync(0xffu, m, off, 8));
        float e = valid ? __expf(t - m) : 0.f;
        float Z = e;
        #pragma unroll
        for (int off = 4; off > 0; off >>= 1)
            Z += __shfl_xor_sync(0xffu, Z, off, 8);
        if (valid) {
            float wk = e / Z;
            s_w[lane] = wk;
            out[(size_t)B_ * N_ * D_ + bn * K_ + lane] = wk;   // qgw
        }
    }
    __syncthreads();

    if (tid < D4_) {
        float4 acc = make_float4(0.f, 0.f, 0.f, 0.f);
        #pragma unroll
        for (int k = 0; k < K_; k++) {
            float wk = s_w[k];
            float4 sv = s_sv[k * D4_ + tid];
            acc.x += wk * sv.x; acc.y += wk * sv.y;
            acc.z += wk * sv.z; acc.w += wk * sv.w;
        }
        ((float4*)out)[(size_t)bn * D4_ + tid] = acc;          // agg
    }
}

extern "C" void kernel_launch(void* const* d_in, const int* in_sizes, int n_in,
                              void* d_out, int out_size) {
    const float4* support = (const float4*)d_in[0];
    const float4* query   = (const float4*)d_in[1];
    float* out = (float*)d_out;

    fused_kernel<<<NBLK_, NT_>>>(query, support, out);
}